// round 12
// baseline (speedup 1.0000x reference)
#include <cuda_runtime.h>
#include <cuda_fp16.h>
#include <math.h>
#include <stdint.h>

#define HEADS 8
#define DIMH  64
#define SEQ   16
#define CH    512
#define BATCH 2048              // b*h*w
#define MROWS (BATCH*SEQ)       // 32768
#define QKVN  1536
#define MEM   4
#define KVLEN 20
#define MP_INV 1.3130643286f    // 1/sqrt(0.58)

typedef __half f16;

// ------------------------- scratch (device globals) -------------------------
// Tiled-swizzled f16 buffers (GEMM operands): layout [rowblk][kchunk][16KB tile],
// tile byte image identical to the smem stage tile (SW128, 128B rows).
__device__ __align__(1024) float g_Y   [(size_t)MROWS*CH];
__device__ __align__(1024) float g_RES [(size_t)MROWS*CH];
__device__ __align__(1024) float g_P   [(size_t)MROWS*CH];
__device__ __align__(1024) f16   g_QKVh[(size_t)MROWS*QKVN];   // linear (attention input)
__device__ __align__(1024) f16   g_Yh  [(size_t)MROWS*CH];     // tiled
__device__ __align__(1024) f16   g_ATh [(size_t)MROWS*CH];     // tiled
__device__ __align__(1024) f16   g_Wq [2*QKVN*CH];             // tiled
__device__ __align__(1024) f16   g_Wo [2*CH*CH];               // tiled
__device__ __align__(1024) f16   g_Wp [CH*CH];                 // tiled

__device__ __forceinline__ uint32_t sw128(uint32_t o) { return o ^ ((o >> 3) & 0x70); }

// element index of (row, ch) in a tiled-swizzled f16 buffer with K=512 (8 chunks)
__device__ __forceinline__ size_t tidx(int row, int ch) {
    uint32_t within = sw128(((uint32_t)(row & 127) << 7) + ((((uint32_t)ch >> 3) & 7) << 4))
                    + (((uint32_t)ch & 7) << 1);               // byte offset in tile
    return ((size_t)((row >> 7) * 8 + (ch >> 6)) << 13) + (within >> 1);
}

// ------------------------- transpose in -------------------------------------
__global__ void transpose_in(const float* __restrict__ x,
                             float* __restrict__ Y, float* __restrict__ RES,
                             f16* __restrict__ Yh) {
    __shared__ float tile[32][33];
    const int b  = blockIdx.z;
    const int t  = blockIdx.y >> 5;
    const int i  = blockIdx.y & 31;
    const int c0 = blockIdx.x << 5;
    const int tx = threadIdx.x, ty = threadIdx.y;   // (32,8)

    const float* xp = x + (((size_t)(b*CH + c0)*SEQ + t)*32 + i)*32;
#pragma unroll
    for (int r = 0; r < 4; r++) {
        int cl = ty + r*8;
        tile[cl][tx] = xp[(size_t)cl*SEQ*32*32 + tx];
    }
    __syncthreads();
#pragma unroll
    for (int r = 0; r < 4; r++) {
        int j = ty + r*8;
        const int row = (b*1024 + i*32 + j)*SEQ + t;
        size_t off = (size_t)row*CH + c0 + tx;
        float v = tile[tx][j];
        Y[off] = v; RES[off] = v;
        Yh[tidx(row, c0 + tx)] = __float2half_rn(v);
    }
}

// ------------------ transpose out + final mp_add ----------------------------
__global__ void transpose_out(const float* __restrict__ P,
                              const float* __restrict__ RES,
                              float* __restrict__ out) {
    __shared__ float tile[32][33];
    const int b  = blockIdx.z;
    const int t  = blockIdx.y >> 5;
    const int i  = blockIdx.y & 31;
    const int c0 = blockIdx.x << 5;
    const int tx = threadIdx.x, ty = threadIdx.y;

#pragma unroll
    for (int r = 0; r < 4; r++) {
        int j = ty + r*8;
        size_t off = ((size_t)(b*1024 + i*32 + j)*SEQ + t)*CH + c0 + tx;
        tile[tx][j] = (P[off]*0.7f + RES[off]*0.3f) * MP_INV;
    }
    __syncthreads();
    float* op = out + (((size_t)(b*CH + c0)*SEQ + t)*32 + i)*32;
#pragma unroll
    for (int r = 0; r < 4; r++) {
        int cl = ty + r*8;
        op[(size_t)cl*SEQ*32*32 + tx] = tile[cl][tx];
    }
}

// ----------------- weight row l2norm -> tiled f16 ---------------------------
__global__ void rownorm(const float* __restrict__ src,
                        f16* __restrict__ dst,
                        const float* __restrict__ gain) {
    const int row = blockIdx.x;
    const int t   = threadIdx.x;            // 128 threads, K=512
    const float4 v = ((const float4*)(src + (size_t)row*CH))[t];
    float ss = v.x*v.x + v.y*v.y + v.z*v.z + v.w*v.w;
#pragma unroll
    for (int o = 16; o; o >>= 1) ss += __shfl_xor_sync(0xffffffffu, ss, o);
    __shared__ float red[4];
    __shared__ float sscale;
    if ((t & 31) == 0) red[t >> 5] = ss;
    __syncthreads();
    if (t == 0) {
        float tot = red[0] + red[1] + red[2] + red[3];
        float sc = 1.f / (fmaxf(sqrtf(tot), 1e-4f) * 22.627416998f); // sqrt(512)
        if (gain) sc *= gain[0];
        sscale = sc;
    }
    __syncthreads();
    const float sc = sscale;
    union { f16 b[4]; uint2 u; } H;
    H.b[0] = __float2half_rn(v.x*sc); H.b[1] = __float2half_rn(v.y*sc);
    H.b[2] = __float2half_rn(v.z*sc); H.b[3] = __float2half_rn(v.w*sc);
    *(uint2*)(dst + tidx(row, 4*t)) = H.u;   // 4 elems within one seg, 8B aligned
}

// ==================== mma.sync fp16 GEMM, cp.async.bulk loads ================
// C[M,N] = A[M,512] @ B[N,512]^T  (fp16 operands, fp32 accum).
// A,B pre-tiled+swizzled in gmem; per chunk ONE 16KB bulk copy per operand.
// CTA tile 128x128, 3-stage, mbarrier complete_tx, 1 __syncthreads per chunk.
// 8 warps 4(M)x2(N); warp tile 32x64; mma m16n8k16. 2 CTAs/SM.
// MODE 0: write f16 Ch linear. MODE 1: blend fp32 C + write tiled f16 Ch.
// MODE 2: write fp32 C only.

#define TILE_B 16384               // one 128row x 128B tile
#define STAGE  (2*TILE_B)          // A, B
#define NSTAGE 3
#define GSMEM  (NSTAGE*STAGE + 64) // stages + mbarriers

__device__ __forceinline__ void ldsm4(uint32_t (&r)[4], uint32_t addr) {
    asm volatile("ldmatrix.sync.aligned.m8n8.x4.shared.b16 {%0,%1,%2,%3}, [%4];"
                 : "=r"(r[0]), "=r"(r[1]), "=r"(r[2]), "=r"(r[3]) : "r"(addr));
}

__device__ __forceinline__ void mma16816(float (&d)[4], const uint32_t (&a)[4],
                                         const uint32_t* b) {
    asm volatile(
        "mma.sync.aligned.m16n8k16.row.col.f32.f16.f16.f32 "
        "{%0,%1,%2,%3}, {%4,%5,%6,%7}, {%8,%9}, {%0,%1,%2,%3};"
        : "+f"(d[0]), "+f"(d[1]), "+f"(d[2]), "+f"(d[3])
        : "r"(a[0]), "r"(a[1]), "r"(a[2]), "r"(a[3]), "r"(b[0]), "r"(b[1]));
}

__device__ __forceinline__ void bulk_ld(uint32_t dst, const void* src, uint32_t mbar) {
    asm volatile(
        "cp.async.bulk.shared::cluster.global.mbarrier::complete_tx::bytes [%0], [%1], %2, [%3];"
        :: "r"(dst), "l"(src), "r"((uint32_t)TILE_B), "r"(mbar) : "memory");
}

__device__ __forceinline__ void mbar_wait(uint32_t mbar, uint32_t parity) {
    asm volatile(
        "{\n\t.reg .pred P;\n\t"
        "WL_%=:\n\t"
        "mbarrier.try_wait.parity.acquire.cta.shared::cta.b64 P, [%0], %1, 0x989680;\n\t"
        "@P bra.uni WD_%=;\n\t"
        "bra.uni WL_%=;\n\t"
        "WD_%=:\n\t}"
        :: "r"(mbar), "r"(parity) : "memory");
}

template<int MODE>
__global__ void __launch_bounds__(256, 2)
gemm_mma(const f16* __restrict__ At, const f16* __restrict__ Bt,
         float* __restrict__ C, f16* __restrict__ Ch,
         int N) {
    extern __shared__ __align__(128) char smem[];
    const uint32_t sb = (uint32_t)__cvta_generic_to_shared(smem);
    const uint32_t mb = sb + NSTAGE*STAGE;
    const int tid   = threadIdx.x;
    const int lane  = tid & 31;
    const int warp  = tid >> 5;
    const int warpM = warp & 3;          // 0..3  -> 32-row slab
    const int warpN = warp >> 2;         // 0..1  -> 64-col slab
    const int m0 = blockIdx.y * 128;
    const int n0 = blockIdx.x * 128;

    if (tid == 0) {
#pragma unroll
        for (int s = 0; s < NSTAGE; s++)
            asm volatile("mbarrier.init.shared.b64 [%0], 1;" :: "r"(mb + s*8) : "memory");
        asm volatile("fence.mbarrier_init.release.cluster;" ::: "memory");
    }
    __syncthreads();

    auto issue = [&](int c) {
        const int s = c % NSTAGE;
        const uint32_t mbar = mb + s*8;
        asm volatile("mbarrier.arrive.expect_tx.shared.b64 _, [%0], %1;"
                     :: "r"(mbar), "r"(2u*TILE_B) : "memory");
        bulk_ld(sb + s*STAGE,          At + ((size_t)((m0 >> 7)*8 + c) << 13), mbar);
        bulk_ld(sb + s*STAGE + TILE_B, Bt + ((size_t)((n0 >> 7)*8 + c) << 13), mbar);
    };

    if (tid == 0) { issue(0); issue(1); }

    float acc[2][8][4];
#pragma unroll
    for (int i = 0; i < 2; i++)
#pragma unroll
        for (int j = 0; j < 8; j++)
#pragma unroll
            for (int e = 0; e < 4; e++) acc[i][j][e] = 0.f;

    // ldmatrix lane addressing (within a 128B-row SW128 tile)
    const int a_row  = (lane & 15);              // + frag*16
    const int a_byte = (lane >> 4) << 4;         // + ks*32
    const int b_row  = (lane & 7) + ((lane >> 4) << 3);   // + group*16
    const int b_byte = ((lane >> 3) & 1) << 4;   // + ks*32

    for (int c = 0; c < 8; c++) {
        mbar_wait(mb + (c % NSTAGE)*8, (c / NSTAGE) & 1);
        __syncthreads();
        // all warps finished compute(c-1) (reader of stage (c+2)%3) above
        if (tid == 0 && c + 2 < 8) issue(c + 2);

        const uint32_t bb = sb + (c % NSTAGE)*STAGE;
#pragma unroll
        for (int ks = 0; ks < 4; ks++) {
            const int kb = ks * 32;
            uint32_t ah[2][4];
#pragma unroll
            for (int mf = 0; mf < 2; mf++) {
                uint32_t ro = (uint32_t)(warpM*32 + mf*16 + a_row)*128 + kb + a_byte;
                ldsm4(ah[mf], bb + sw128(ro));
            }
            uint32_t bh[8][2];
#pragma unroll
            for (int g = 0; g < 4; g++) {
                uint32_t ro = (uint32_t)(warpN*64 + g*16 + b_row)*128 + kb + b_byte;
                uint32_t t[4];
                ldsm4(t, bb + TILE_B + sw128(ro));
                bh[2*g][0] = t[0]; bh[2*g][1] = t[1];
                bh[2*g+1][0] = t[2]; bh[2*g+1][1] = t[3];
            }
#pragma unroll
            for (int mf = 0; mf < 2; mf++)
#pragma unroll
                for (int nf = 0; nf < 8; nf++)
                    mma16816(acc[mf][nf], ah[mf], bh[nf]);
        }
    }

    // ------------------------------ epilogue --------------------------------
    const int mr = m0 + warpM*32 + (lane >> 2);
    const int nc = n0 + warpN*64 + (lane & 3)*2;
#pragma unroll
    for (int mf = 0; mf < 2; mf++)
#pragma unroll
        for (int nf = 0; nf < 8; nf++)
#pragma unroll
            for (int half = 0; half < 2; half++) {
                const int m = mr + mf*16 + half*8;
                const int n = nc + nf*8;
                float v0 = acc[mf][nf][half*2 + 0];
                float v1 = acc[mf][nf][half*2 + 1];
                if (MODE == 0) {
                    union { f16 b[2]; uint32_t u; } H;
                    H.b[0] = __float2half_rn(v0);
                    H.b[1] = __float2half_rn(v1);
                    *(uint32_t*)(Ch + (size_t)m*N + n) = H.u;
                } else if (MODE == 2) {
                    *(float2*)(C + (size_t)m*N + n) = make_float2(v0, v1);
                } else {
                    float* Cp = C + (size_t)m*N + n;
                    float2 old = *(const float2*)Cp;
                    v0 = (v0*0.7f + old.x*0.3f)*MP_INV;
                    v1 = (v1*0.7f + old.y*0.3f)*MP_INV;
                    *(float2*)Cp = make_float2(v0, v1);
                    union { f16 b[2]; uint32_t u; } H;
                    H.b[0] = __float2half_rn(v0);
                    H.b[1] = __float2half_rn(v1);
                    *(uint32_t*)(Ch + tidx(m, n)) = H.u;   // tiled (next GEMM's A)
                }
            }
}

// ------------------------- fused attention ----------------------------------
// 128 threads per block, 1 block per batch element: 4 warps = 4 head-pairs.
__global__ void attention(const f16* __restrict__ QKVh,
                          const float* __restrict__ memkv,
                          f16* __restrict__ Oh) {
    __shared__ float ks[HEADS][KVLEN];
    __shared__ float vs[HEADS][KVLEN];
    const int bt  = blockIdx.x;
    const int tid = threadIdx.x;
    const float* memk = memkv;
    const float* memv = memkv + HEADS*MEM*DIMH;

    // ---- phase 1: per-row pixel-norm scales (8 heads x 20 rows x {K,V}) ----
    for (int r = tid; r < 2*HEADS*KVLEN; r += 128) {
        const int head = r / (2*KVLEN);
        const int rem  = r % (2*KVLEN);
        const int kv   = rem / KVLEN;          // 0=K, 1=V
        const int row  = rem % KVLEN;
        float ss = 0.f;
        if (row < MEM) {
            const float4* p = (const float4*)((kv ? memv : memk)
                              + ((size_t)head*MEM + row)*DIMH);
#pragma unroll
            for (int d4 = 0; d4 < DIMH/4; d4++) {
                float4 v = p[d4];
                ss += v.x*v.x + v.y*v.y + v.z*v.z + v.w*v.w;
            }
        } else {
            const f16* p = QKVh + ((size_t)bt*SEQ + row - MEM)*QKVN
                         + (kv ? 2*CH : CH) + head*DIMH;
#pragma unroll
            for (int d = 0; d < DIMH; d += 2) {
                float a = __half2float(p[d]), b = __half2float(p[d+1]);
                ss += a*a + b*b;
            }
        }
        float s = 8.f / fmaxf(sqrtf(ss), 1e-4f);
        if (kv) vs[head][row] = s; else ks[head][row] = s;
    }
    __syncthreads();

    // ---- phase 2 ----
    const int warp = tid >> 5;
    const int lane = tid & 31;
    const int hh   = lane >> 4;
    const int row  = lane & 15;
    const int head = warp*2 + hh;

    const f16* qp = QKVh + ((size_t)bt*SEQ + row)*QKVN + head*DIMH;
    float q[DIMH];
    float ssq = 0.f;
#pragma unroll
    for (int d = 0; d < DIMH; d++) {
        float v = __half2float(qp[d]);
        q[d] = v; ssq += v*v;
    }
    const float qs = 1.f / fmaxf(sqrtf(ssq), 1e-4f);  // pixel_norm(q)*D^-1/2 == l2norm

    float sc[KVLEN];
    float mx = -1e30f;
#pragma unroll
    for (int j = 0; j < MEM; j++) {
        const float* kp = memk + ((size_t)head*MEM + j)*DIMH;
        float dot = 0.f;
#pragma unroll
        for (int d = 0; d < DIMH; d++) dot += q[d]*kp[d];
        dot *= qs * ks[head][j];
        sc[j] = dot; mx = fmaxf(mx, dot);
    }
#pragma unroll
    for (int j = MEM; j < KVLEN; j++) {
        const f16* kp = QKVh + ((size_t)bt*SEQ + j - MEM)*QKVN + CH + head*DIMH;
        float dot = 0.f;
#pragma unroll
        for (int d = 0; d < DIMH; d++) dot += q[d]*__half2float(kp[d]);
        dot *= qs * ks[head][j];
        sc[j] = dot; mx = fmaxf(mx, dot);
    }
    float sum = 0.f;
#pragma unroll
    for (int j = 0; j < KVLEN; j++) { sc[j] = expf(sc[j] - mx); sum += sc[j]; }
    const float inv = 1.f / sum;

    float o[DIMH];
#pragma unroll
    for (int d = 0; d < DIMH; d++) o[d] = 0.f;
#pragma unroll
    for (int j = 0; j < MEM; j++) {
        const float* vp = memv + ((size_t)head*MEM + j)*DIMH;
        const float p = sc[j] * vs[head][j];
#pragma unroll
        for (int d = 0; d < DIMH; d++) o[d] += p * vp[d];
    }
#pragma unroll
    for (int j = MEM; j < KVLEN; j++) {
        const f16* vp = QKVh + ((size_t)bt*SEQ + j - MEM)*QKVN + 2*CH + head*DIMH;
        const float p = sc[j] * vs[head][j];
#pragma unroll
        for (int d = 0; d < DIMH; d++) o[d] += p * __half2float(vp[d]);
    }
    const int grow = bt*SEQ + row;
#pragma unroll
    for (int d4 = 0; d4 < DIMH/4; d4++) {
        union { f16 b[4]; uint2 u; } H;
#pragma unroll
        for (int i = 0; i < 4; i++)
            H.b[i] = __float2half_rn(o[4*d4+i]*inv);
        *(uint2*)(Oh + tidx(grow, head*DIMH + 4*d4)) = H.u;   // tiled
    }
}

// ------------------------------- launcher ------------------------------------
extern "C" void kernel_launch(void* const* d_in, const int* in_sizes, int n_in,
                              void* d_out, int out_size) {
    const float* x      = (const float*)d_in[0];
    const float* w_qkv  = (const float*)d_in[1];
    const float* w_out  = (const float*)d_in[2];
    const float* mem_kv = (const float*)d_in[3];
    const float* w_proj = (const float*)d_in[4];
    const float* gain   = (const float*)d_in[5];
    float* out = (float*)d_out;

    float *Y, *RES, *P;
    f16 *QKVh, *Yh, *ATh, *Wq, *Wo, *Wp;
    cudaGetSymbolAddress((void**)&Y,    g_Y);
    cudaGetSymbolAddress((void**)&RES,  g_RES);
    cudaGetSymbolAddress((void**)&P,    g_P);
    cudaGetSymbolAddress((void**)&QKVh, g_QKVh);
    cudaGetSymbolAddress((void**)&Yh,   g_Yh);
    cudaGetSymbolAddress((void**)&ATh,  g_ATh);
    cudaGetSymbolAddress((void**)&Wq,   g_Wq);
    cudaGetSymbolAddress((void**)&Wo,   g_Wo);
    cudaGetSymbolAddress((void**)&Wp,   g_Wp);

    cudaFuncSetAttribute(gemm_mma<0>, cudaFuncAttributeMaxDynamicSharedMemorySize, GSMEM);
    cudaFuncSetAttribute(gemm_mma<1>, cudaFuncAttributeMaxDynamicSharedMemorySize, GSMEM);
    cudaFuncSetAttribute(gemm_mma<2>, cudaFuncAttributeMaxDynamicSharedMemorySize, GSMEM);

    const dim3 tb(32, 8);
    const dim3 tg(16, 512, 2);

    transpose_in<<<tg, tb>>>(x, Y, RES, Yh);

    rownorm<<<2*QKVN, 128>>>(w_qkv,  Wq, nullptr);
    rownorm<<<2*CH,   128>>>(w_out,  Wo, nullptr);
    rownorm<<<CH,     128>>>(w_proj, Wp, gain);

    for (int l = 0; l < 2; l++) {
        gemm_mma<0><<<dim3(QKVN/128, MROWS/128), 256, GSMEM>>>(
            Yh, Wq + (size_t)l*QKVN*CH, nullptr, QKVh, QKVN);
        attention<<<BATCH, 128>>>(
            QKVh, mem_kv + (size_t)l*2*HEADS*MEM*DIMH, ATh);
        gemm_mma<1><<<dim3(CH/128, MROWS/128), 256, GSMEM>>>(
            ATh, Wo + (size_t)l*CH*CH, Y, Yh, CH);
    }

    gemm_mma<2><<<dim3(CH/128, MROWS/128), 256, GSMEM>>>(
        Yh, Wp, P, nullptr, CH);
    transpose_out<<<tg, tb>>>(P, RES, out);
}

// round 13
// speedup vs baseline: 1.3291x; 1.3291x over previous
#include <cuda_runtime.h>
#include <cuda_fp16.h>
#include <math.h>
#include <stdint.h>

#define HEADS 8
#define DIMH  64
#define SEQ   16
#define CH    512
#define BATCH 2048              // b*h*w
#define MROWS (BATCH*SEQ)       // 32768
#define QKVN  1536
#define MEM   4
#define KVLEN 20
#define MP_INV 1.3130643286f    // 1/sqrt(0.58)

typedef __half f16;

// ------------------------- scratch (device globals) -------------------------
// Tiled-swizzled f16 buffers (GEMM operands): layout [rowblk][kchunk][16KB tile],
// tile byte image identical to the smem stage tile (SW128, 128B rows).
__device__ __align__(1024) f16   g_RESh[(size_t)MROWS*CH];     // linear
__device__ __align__(1024) f16   g_Ph  [(size_t)MROWS*CH];     // linear
__device__ __align__(1024) f16   g_QKVh[(size_t)MROWS*QKVN];   // linear, NORMALIZED
__device__ __align__(1024) f16   g_Yh  [(size_t)MROWS*CH];     // tiled (running state)
__device__ __align__(1024) f16   g_ATh [(size_t)MROWS*CH];     // tiled
__device__ __align__(1024) f16   g_Wq [2*QKVN*CH];             // tiled
__device__ __align__(1024) f16   g_Wo [2*CH*CH];               // tiled
__device__ __align__(1024) f16   g_Wp [CH*CH];                 // tiled

__device__ __forceinline__ uint32_t sw128(uint32_t o) { return o ^ ((o >> 3) & 0x70); }

// element index of (row, ch) in a tiled-swizzled f16 buffer with K=512 (8 chunks)
__device__ __forceinline__ size_t tidx(int row, int ch) {
    uint32_t within = sw128(((uint32_t)(row & 127) << 7) + ((((uint32_t)ch >> 3) & 7) << 4))
                    + (((uint32_t)ch & 7) << 1);               // byte offset in tile
    return ((size_t)((row >> 7) * 8 + (ch >> 6)) << 13) + (within >> 1);
}

// ------------------------- transpose in -------------------------------------
__global__ void transpose_in(const float* __restrict__ x,
                             f16* __restrict__ RESh, f16* __restrict__ Yh) {
    __shared__ float tile[32][33];
    const int b  = blockIdx.z;
    const int t  = blockIdx.y >> 5;
    const int i  = blockIdx.y & 31;
    const int c0 = blockIdx.x << 5;
    const int tx = threadIdx.x, ty = threadIdx.y;   // (32,8)

    const float* xp = x + (((size_t)(b*CH + c0)*SEQ + t)*32 + i)*32;
#pragma unroll
    for (int r = 0; r < 4; r++) {
        int cl = ty + r*8;
        tile[cl][tx] = xp[(size_t)cl*SEQ*32*32 + tx];
    }
    __syncthreads();
#pragma unroll
    for (int r = 0; r < 4; r++) {
        int j = ty + r*8;
        const int row = (b*1024 + i*32 + j)*SEQ + t;
        float v = tile[tx][j];
        f16 h = __float2half_rn(v);
        RESh[(size_t)row*CH + c0 + tx] = h;
        Yh[tidx(row, c0 + tx)] = h;
    }
}

// ------------------ transpose out + final mp_add ----------------------------
__global__ void transpose_out(const f16* __restrict__ Ph,
                              const f16* __restrict__ RESh,
                              float* __restrict__ out) {
    __shared__ float tile[32][33];
    const int b  = blockIdx.z;
    const int t  = blockIdx.y >> 5;
    const int i  = blockIdx.y & 31;
    const int c0 = blockIdx.x << 5;
    const int tx = threadIdx.x, ty = threadIdx.y;

#pragma unroll
    for (int r = 0; r < 4; r++) {
        int j = ty + r*8;
        size_t off = ((size_t)(b*1024 + i*32 + j)*SEQ + t)*CH + c0 + tx;
        tile[tx][j] = (__half2float(Ph[off])*0.7f
                     + __half2float(RESh[off])*0.3f) * MP_INV;
    }
    __syncthreads();
    float* op = out + (((size_t)(b*CH + c0)*SEQ + t)*32 + i)*32;
#pragma unroll
    for (int r = 0; r < 4; r++) {
        int cl = ty + r*8;
        op[(size_t)cl*SEQ*32*32 + tx] = tile[cl][tx];
    }
}

// ----------------- weight row l2norm -> tiled f16 ---------------------------
__global__ void rownorm(const float* __restrict__ src,
                        f16* __restrict__ dst,
                        const float* __restrict__ gain) {
    const int row = blockIdx.x;
    const int t   = threadIdx.x;            // 128 threads, K=512
    const float4 v = ((const float4*)(src + (size_t)row*CH))[t];
    float ss = v.x*v.x + v.y*v.y + v.z*v.z + v.w*v.w;
#pragma unroll
    for (int o = 16; o; o >>= 1) ss += __shfl_xor_sync(0xffffffffu, ss, o);
    __shared__ float red[4];
    __shared__ float sscale;
    if ((t & 31) == 0) red[t >> 5] = ss;
    __syncthreads();
    if (t == 0) {
        float tot = red[0] + red[1] + red[2] + red[3];
        float sc = 1.f / (fmaxf(sqrtf(tot), 1e-4f) * 22.627416998f); // sqrt(512)
        if (gain) sc *= gain[0];
        sscale = sc;
    }
    __syncthreads();
    const float sc = sscale;
    union { f16 b[4]; uint2 u; } H;
    H.b[0] = __float2half_rn(v.x*sc); H.b[1] = __float2half_rn(v.y*sc);
    H.b[2] = __float2half_rn(v.z*sc); H.b[3] = __float2half_rn(v.w*sc);
    *(uint2*)(dst + tidx(row, 4*t)) = H.u;
}

// ==================== mma.sync fp16 GEMM =====================================
// C[M,N] = A[M,512] @ B[N,512]^T  (fp16 operands, fp32 accum).
// A,B pre-tiled+swizzled in gmem -> contiguous cp.async 16B loads, 3 stages.
// CTA tile 128x128; 8 warps 4(M)x2(N); warp tile 32x64; 2 CTAs/SM.
// MODE 0: QKV — per-(row,head) pixel/l2 norm fused in epilogue, write f16 linear.
// MODE 1: out-proj — mp_add blend with old tiled f16 state, write tiled f16.
// MODE 2: final proj — write f16 linear.

#define TILE_B 16384               // one 128row x 128B tile
#define STAGE  (2*TILE_B)          // A, B
#define NSTAGE 3
#define GSMEM  (NSTAGE*STAGE)      // 98304

__device__ __forceinline__ void cp16(uint32_t dst, const void* src) {
    asm volatile("cp.async.cg.shared.global [%0], [%1], 16;\n" :: "r"(dst), "l"(src));
}
#define CP_COMMIT() asm volatile("cp.async.commit_group;\n" ::: "memory")
#define CP_WAIT(n)  asm volatile("cp.async.wait_group %0;\n" :: "n"(n) : "memory")

__device__ __forceinline__ void ldsm4(uint32_t (&r)[4], uint32_t addr) {
    asm volatile("ldmatrix.sync.aligned.m8n8.x4.shared.b16 {%0,%1,%2,%3}, [%4];"
                 : "=r"(r[0]), "=r"(r[1]), "=r"(r[2]), "=r"(r[3]) : "r"(addr));
}

__device__ __forceinline__ void mma16816(float (&d)[4], const uint32_t (&a)[4],
                                         const uint32_t* b) {
    asm volatile(
        "mma.sync.aligned.m16n8k16.row.col.f32.f16.f16.f32 "
        "{%0,%1,%2,%3}, {%4,%5,%6,%7}, {%8,%9}, {%0,%1,%2,%3};"
        : "+f"(d[0]), "+f"(d[1]), "+f"(d[2]), "+f"(d[3])
        : "r"(a[0]), "r"(a[1]), "r"(a[2]), "r"(a[3]), "r"(b[0]), "r"(b[1]));
}

template<int MODE>
__global__ void __launch_bounds__(256, 2)
gemm_mma(const f16* __restrict__ At, const f16* __restrict__ Bt,
         f16* __restrict__ Ch, int N) {
    extern __shared__ __align__(128) char smem[];
    const uint32_t sb = (uint32_t)__cvta_generic_to_shared(smem);
    const int tid   = threadIdx.x;
    const int lane  = tid & 31;
    const int warp  = tid >> 5;
    const int warpM = warp & 3;          // 0..3  -> 32-row slab
    const int warpN = warp >> 2;         // 0..1  -> 64-col slab
    const int m0 = blockIdx.y * 128;
    const int n0 = blockIdx.x * 128;

    auto load_chunk = [&](int c, int buf) {
        const uint32_t bb = sb + buf*STAGE;
        const char* Asrc = (const char*)(At + ((size_t)((m0 >> 7)*8 + c) << 13));
        const char* Bsrc = (const char*)(Bt + ((size_t)((n0 >> 7)*8 + c) << 13));
#pragma unroll
        for (int i = tid; i < 1024; i += 256) {
            cp16(bb + i*16,          Asrc + i*16);
            cp16(bb + TILE_B + i*16, Bsrc + i*16);
        }
        CP_COMMIT();
    };

    load_chunk(0, 0);
    load_chunk(1, 1);

    float acc[2][8][4];
#pragma unroll
    for (int i = 0; i < 2; i++)
#pragma unroll
        for (int j = 0; j < 8; j++)
#pragma unroll
            for (int e = 0; e < 4; e++) acc[i][j][e] = 0.f;

    // ldmatrix lane addressing (within a 128B-row SW128 tile)
    const int a_row  = (lane & 15);              // + frag*16
    const int a_byte = (lane >> 4) << 4;         // + ks*32
    const int b_row  = (lane & 7) + ((lane >> 4) << 3);   // + group*16
    const int b_byte = ((lane >> 3) & 1) << 4;   // + ks*32

    for (int c = 0; c < 8; c++) {
        if (c < 7) { CP_WAIT(1); } else { CP_WAIT(0); }
        __syncthreads();
        // all warps finished compute(c-1) (reader of stage (c+2)%3) above
        if (c + 2 < 8) load_chunk(c + 2, (c + 2) % NSTAGE);

        const uint32_t bb = sb + (c % NSTAGE)*STAGE;
#pragma unroll
        for (int ks = 0; ks < 4; ks++) {
            const int kb = ks * 32;
            uint32_t ah[2][4];
#pragma unroll
            for (int mf = 0; mf < 2; mf++) {
                uint32_t ro = (uint32_t)(warpM*32 + mf*16 + a_row)*128 + kb + a_byte;
                ldsm4(ah[mf], bb + sw128(ro));
            }
            uint32_t bh[8][2];
#pragma unroll
            for (int g = 0; g < 4; g++) {
                uint32_t ro = (uint32_t)(warpN*64 + g*16 + b_row)*128 + kb + b_byte;
                uint32_t t[4];
                ldsm4(t, bb + TILE_B + sw128(ro));
                bh[2*g][0] = t[0]; bh[2*g][1] = t[1];
                bh[2*g+1][0] = t[2]; bh[2*g+1][1] = t[3];
            }
#pragma unroll
            for (int mf = 0; mf < 2; mf++)
#pragma unroll
                for (int nf = 0; nf < 8; nf++)
                    mma16816(acc[mf][nf], ah[mf], bh[nf]);
        }
    }

    // ------------------------------ epilogue --------------------------------
    const int mr = m0 + warpM*32 + (lane >> 2);
    const int nc = n0 + warpN*64 + (lane & 3)*2;

    if (MODE == 0) {
        // one warp column-slab (64 cols) == exactly one head: fused pixel/l2 norm.
        // seg 0 = Q -> l2norm (D^-1/2 folded); seg 1,2 = K,V -> pixel_norm (x8).
        const int seg = (n0 + warpN*64) >> 9;
        const float num = (seg == 0) ? 1.f : 8.f;
#pragma unroll
        for (int mf = 0; mf < 2; mf++)
#pragma unroll
            for (int half = 0; half < 2; half++) {
                const int m = mr + mf*16 + half*8;
                float ss = 0.f;
#pragma unroll
                for (int nf = 0; nf < 8; nf++) {
                    float a = acc[mf][nf][half*2 + 0];
                    float b = acc[mf][nf][half*2 + 1];
                    ss += a*a + b*b;
                }
                ss += __shfl_xor_sync(0xffffffffu, ss, 1);
                ss += __shfl_xor_sync(0xffffffffu, ss, 2);
                const float s = num / fmaxf(sqrtf(ss), 1e-4f);
#pragma unroll
                for (int nf = 0; nf < 8; nf++) {
                    union { f16 b[2]; uint32_t u; } H;
                    H.b[0] = __float2half_rn(acc[mf][nf][half*2 + 0]*s);
                    H.b[1] = __float2half_rn(acc[mf][nf][half*2 + 1]*s);
                    *(uint32_t*)(Ch + (size_t)m*N + nc + nf*8) = H.u;
                }
            }
    } else {
#pragma unroll
        for (int mf = 0; mf < 2; mf++)
#pragma unroll
            for (int nf = 0; nf < 8; nf++)
#pragma unroll
                for (int half = 0; half < 2; half++) {
                    const int m = mr + mf*16 + half*8;
                    const int n = nc + nf*8;
                    float v0 = acc[mf][nf][half*2 + 0];
                    float v1 = acc[mf][nf][half*2 + 1];
                    if (MODE == 2) {
                        union { f16 b[2]; uint32_t u; } H;
                        H.b[0] = __float2half_rn(v0);
                        H.b[1] = __float2half_rn(v1);
                        *(uint32_t*)(Ch + (size_t)m*N + n) = H.u;
                    } else {        // MODE 1: blend with old tiled state
                        uint32_t* sp = (uint32_t*)(Ch + tidx(m, n));
                        union { f16 b[2]; uint32_t u; } O;
                        O.u = *sp;
                        v0 = (v0*0.7f + __half2float(O.b[0])*0.3f)*MP_INV;
                        v1 = (v1*0.7f + __half2float(O.b[1])*0.3f)*MP_INV;
                        union { f16 b[2]; uint32_t u; } H;
                        H.b[0] = __float2half_rn(v0);
                        H.b[1] = __float2half_rn(v1);
                        *sp = H.u;
                    }
                }
    }
}

// ------------------------- fused attention ----------------------------------
// QKVh is PRE-NORMALIZED (q l2normed; k,v pixel-normed) by the QKV epilogue.
// 128 threads per block, 1 block per batch element: 4 warps = 4 head-pairs.
__global__ void attention(const f16* __restrict__ QKVh,
                          const float* __restrict__ memkv,
                          f16* __restrict__ Oh) {
    __shared__ float ks[HEADS][MEM];
    __shared__ float vs[HEADS][MEM];
    const int bt  = blockIdx.x;
    const int tid = threadIdx.x;
    const float* memk = memkv;
    const float* memv = memkv + HEADS*MEM*DIMH;

    // ---- phase 1: pixel-norm scales for the 64 memory K/V rows only --------
    if (tid < 2*HEADS*MEM) {
        const int head = tid >> 3;
        const int kv   = (tid >> 2) & 1;
        const int row  = tid & 3;
        const float4* p = (const float4*)((kv ? memv : memk)
                          + ((size_t)head*MEM + row)*DIMH);
        float ss = 0.f;
#pragma unroll
        for (int d4 = 0; d4 < DIMH/4; d4++) {
            float4 v = p[d4];
            ss += v.x*v.x + v.y*v.y + v.z*v.z + v.w*v.w;
        }
        float s = 8.f / fmaxf(sqrtf(ss), 1e-4f);
        if (kv) vs[head][row] = s; else ks[head][row] = s;
    }
    __syncthreads();

    // ---- phase 2 ----
    const int warp = tid >> 5;
    const int lane = tid & 31;
    const int hh   = lane >> 4;
    const int row  = lane & 15;
    const int head = warp*2 + hh;

    const f16* qp = QKVh + ((size_t)bt*SEQ + row)*QKVN + head*DIMH;
    float q[DIMH];
#pragma unroll
    for (int d = 0; d < DIMH; d++) q[d] = __half2float(qp[d]);

    float sc[KVLEN];
    float mx = -1e30f;
#pragma unroll
    for (int j = 0; j < MEM; j++) {
        const float* kp = memk + ((size_t)head*MEM + j)*DIMH;
        float dot = 0.f;
#pragma unroll
        for (int d = 0; d < DIMH; d++) dot += q[d]*kp[d];
        dot *= ks[head][j];
        sc[j] = dot; mx = fmaxf(mx, dot);
    }
#pragma unroll
    for (int j = MEM; j < KVLEN; j++) {
        const f16* kp = QKVh + ((size_t)bt*SEQ + j - MEM)*QKVN + CH + head*DIMH;
        float dot = 0.f;
#pragma unroll
        for (int d = 0; d < DIMH; d++) dot += q[d]*__half2float(kp[d]);
        sc[j] = dot; mx = fmaxf(mx, dot);
    }
    float sum = 0.f;
#pragma unroll
    for (int j = 0; j < KVLEN; j++) { sc[j] = expf(sc[j] - mx); sum += sc[j]; }
    const float inv = 1.f / sum;

    float o[DIMH];
#pragma unroll
    for (int d = 0; d < DIMH; d++) o[d] = 0.f;
#pragma unroll
    for (int j = 0; j < MEM; j++) {
        const float* vp = memv + ((size_t)head*MEM + j)*DIMH;
        const float p = sc[j] * vs[head][j];
#pragma unroll
        for (int d = 0; d < DIMH; d++) o[d] += p * vp[d];
    }
#pragma unroll
    for (int j = MEM; j < KVLEN; j++) {
        const f16* vp = QKVh + ((size_t)bt*SEQ + j - MEM)*QKVN + 2*CH + head*DIMH;
        const float p = sc[j];
#pragma unroll
        for (int d = 0; d < DIMH; d++) o[d] += p * __half2float(vp[d]);
    }
    const int grow = bt*SEQ + row;
#pragma unroll
    for (int d4 = 0; d4 < DIMH/4; d4++) {
        union { f16 b[4]; uint2 u; } H;
#pragma unroll
        for (int i = 0; i < 4; i++)
            H.b[i] = __float2half_rn(o[4*d4+i]*inv);
        *(uint2*)(Oh + tidx(grow, head*DIMH + 4*d4)) = H.u;   // tiled
    }
}

// ------------------------------- launcher ------------------------------------
extern "C" void kernel_launch(void* const* d_in, const int* in_sizes, int n_in,
                              void* d_out, int out_size) {
    const float* x      = (const float*)d_in[0];
    const float* w_qkv  = (const float*)d_in[1];
    const float* w_out  = (const float*)d_in[2];
    const float* mem_kv = (const float*)d_in[3];
    const float* w_proj = (const float*)d_in[4];
    const float* gain   = (const float*)d_in[5];
    float* out = (float*)d_out;

    f16 *RESh, *Ph, *QKVh, *Yh, *ATh, *Wq, *Wo, *Wp;
    cudaGetSymbolAddress((void**)&RESh, g_RESh);
    cudaGetSymbolAddress((void**)&Ph,   g_Ph);
    cudaGetSymbolAddress((void**)&QKVh, g_QKVh);
    cudaGetSymbolAddress((void**)&Yh,   g_Yh);
    cudaGetSymbolAddress((void**)&ATh,  g_ATh);
    cudaGetSymbolAddress((void**)&Wq,   g_Wq);
    cudaGetSymbolAddress((void**)&Wo,   g_Wo);
    cudaGetSymbolAddress((void**)&Wp,   g_Wp);

    cudaFuncSetAttribute(gemm_mma<0>, cudaFuncAttributeMaxDynamicSharedMemorySize, GSMEM);
    cudaFuncSetAttribute(gemm_mma<1>, cudaFuncAttributeMaxDynamicSharedMemorySize, GSMEM);
    cudaFuncSetAttribute(gemm_mma<2>, cudaFuncAttributeMaxDynamicSharedMemorySize, GSMEM);

    const dim3 tb(32, 8);
    const dim3 tg(16, 512, 2);

    transpose_in<<<tg, tb>>>(x, RESh, Yh);

    rownorm<<<2*QKVN, 128>>>(w_qkv,  Wq, nullptr);
    rownorm<<<2*CH,   128>>>(w_out,  Wo, nullptr);
    rownorm<<<CH,     128>>>(w_proj, Wp, gain);

    for (int l = 0; l < 2; l++) {
        gemm_mma<0><<<dim3(QKVN/128, MROWS/128), 256, GSMEM>>>(
            Yh, Wq + (size_t)l*QKVN*CH, QKVh, QKVN);
        attention<<<BATCH, 128>>>(
            QKVh, mem_kv + (size_t)l*2*HEADS*MEM*DIMH, ATh);
        gemm_mma<1><<<dim3(CH/128, MROWS/128), 256, GSMEM>>>(
            ATh, Wo + (size_t)l*CH*CH, Yh, CH);
    }

    gemm_mma<2><<<dim3(CH/128, MROWS/128), 256, GSMEM>>>(
        Yh, Wp, Ph, CH);
    transpose_out<<<tg, tb>>>(Ph, RESh, out);
}